// round 9
// baseline (speedup 1.0000x reference)
#include <cuda_runtime.h>
#include <cuda_fp16.h>
#include <cstdint>
#include <math.h>

// ---------------- problem constants ----------------
#define BATCH 16
#define EDIM  256
#define HWSZ  4096
#define NPIX  65536
#define RNUM  365
#define KSEG  512            // fp16 split-2: A'=[hi|lo], B'=[hi|hi]
#define NT_R  32
#define NCOLS 96             // 3 modes * 32 r
#define NTILES 12
#define MPX   128
#define NCHUNK 8             // 512 / 64

#define TOT1     ((size_t)BATCH * RNUM * HWSZ)
#define OFF_CLS    ((size_t)0)
#define OFF_CLSNEG (TOT1)
#define OFF_DIST   (2*TOT1)
#define OFF_DNEG   (3*TOT1)
#define OFF_PORI   (5*TOT1)

// ---------------- static device scratch ----------------
__device__ __half g_xth[(size_t)NPIX * KSEG];              // 64 MB  x transposed, fp16 [hi|lo]
__device__ __half g_embA[(size_t)NPIX * KSEG];             // 64 MB  emb split [hi|lo]
__device__ __half g_B[(size_t)NTILES * NCOLS * KSEG];      // 1.2 MB reps [hi|hi]
__device__ float g_part[NTILES][NPIX];
__device__ float g_sum[NPIX];

// ---------------- helpers ----------------
__device__ __forceinline__ uint32_t pk_hf2(__half a, __half b) {
    unsigned short ua = __half_as_ushort(a), ub = __half_as_ushort(b);
    return (uint32_t)ua | ((uint32_t)ub << 16);
}
__device__ __forceinline__ uint32_t smem_u32(const void* p) {
    uint32_t a;
    asm("{ .reg .u64 t; cvta.to.shared.u64 t, %1; cvt.u32.u64 %0, t; }" : "=r"(a) : "l"(p));
    return a;
}
__device__ __forceinline__ uint2 cvt_f4h(float4 v, bool lo) {
    __half h0 = __float2half(v.x), h1 = __float2half(v.y),
           h2 = __float2half(v.z), h3 = __float2half(v.w);
    if (lo) {
        h0 = __float2half(v.x - __half2float(h0));
        h1 = __float2half(v.y - __half2float(h1));
        h2 = __float2half(v.z - __half2float(h2));
        h3 = __float2half(v.w - __half2float(h3));
    }
    uint2 r; r.x = pk_hf2(h0, h1); r.y = pk_hf2(h2, h3); return r;
}

#define LDSM_X4(r0, r1, r2, r3, addr)                                          \
    asm volatile("ldmatrix.sync.aligned.m8n8.x4.shared.b16 {%0,%1,%2,%3}, [%4];" \
        : "=r"(r0), "=r"(r1), "=r"(r2), "=r"(r3) : "r"(addr))

#define MMA_F16(c, a, b0, b1)                                                  \
    asm volatile("mma.sync.aligned.m16n8k16.row.col.f32.f16.f16.f32 "          \
        "{%0,%1,%2,%3}, {%4,%5,%6,%7}, {%8,%9}, {%0,%1,%2,%3};"                \
        : "+f"((c)[0]), "+f"((c)[1]), "+f"((c)[2]), "+f"((c)[3])               \
        : "r"((a)[0]), "r"((a)[1]), "r"((a)[2]), "r"((a)[3]), "r"(b0), "r"(b1))

// streaming (evict-first) store: protects L2 residency of g_embA
#define STG_CS(addr, val)                                                      \
    asm volatile("st.global.cs.f32 [%0], %1;" :: "l"(addr), "f"(val))

// =====================================================================
// Kernel 0: transpose x[b][c][hw] -> g_xth[b*4096+hw][c] fp16 [hi|lo]
// =====================================================================
__global__ __launch_bounds__(256) void transpose_kernel(const float* __restrict__ x)
{
    __shared__ float tl[32][33];
    const int hw0 = blockIdx.x * 32, c0 = blockIdx.y * 32, b = blockIdx.z;
    const int tx = threadIdx.x & 31, ty = threadIdx.x >> 5;
    const float* src = x + ((size_t)b * 256 + c0) * 4096 + hw0;
    #pragma unroll
    for (int j = 0; j < 4; j++)
        tl[ty * 4 + j][tx] = src[(size_t)(ty * 4 + j) * 4096 + tx];
    __syncthreads();
    #pragma unroll
    for (int j = 0; j < 4; j++) {
        float v = tl[tx][ty * 4 + j];
        __half hi = __float2half(v);
        __half lo = __float2half(v - __half2float(hi));
        size_t rowb = ((size_t)b * 4096 + hw0 + ty * 4 + j) * KSEG + c0 + tx;
        g_xth[rowb]       = hi;
        g_xth[rowb + 256] = lo;
    }
}

// =====================================================================
// Kernel 1: build B' (pos / neg0 / neg1, normalized, fp16 [hi|hi]).
// B layout: [tile(12)][col(96) = mode*32 + (r&31)][KSEG]
// =====================================================================
__global__ __launch_bounds__(256) void prep_reps_kernel(
    const float* __restrict__ reps,
    const float* __restrict__ negw,
    const float* __restrict__ negb)
{
    __shared__ float s_rep[8][256];
    __shared__ float s_off[8][512];
    const int tid = threadIdx.x;
    const int r0 = blockIdx.x * 8;
    const int w = tid >> 5, lane = tid & 31;

    #pragma unroll
    for (int i = 0; i < 8; i++) {
        int r = r0 + i;
        s_rep[i][tid] = (r < RNUM) ? reps[r * 256 + tid] : 0.f;
    }
    __syncthreads();

    for (int jj = 0; jj < 64; jj++) {
        int j = w * 64 + jj;
        float part[8];
        #pragma unroll
        for (int rl = 0; rl < 8; rl++) part[rl] = 0.f;
        #pragma unroll
        for (int i2 = 0; i2 < 8; i2++) {
            int k = lane + 32 * i2;
            float wv = negw[j * 256 + k];
            #pragma unroll
            for (int rl = 0; rl < 8; rl++) part[rl] += wv * fabsf(s_rep[rl][k]);
        }
        #pragma unroll
        for (int off = 16; off > 0; off >>= 1) {
            #pragma unroll
            for (int rl = 0; rl < 8; rl++)
                part[rl] += __shfl_xor_sync(0xffffffffu, part[rl], off);
        }
        if (lane < 8) s_off[lane][j] = part[lane] + negb[j];
    }
    __syncthreads();

    #pragma unroll
    for (int pi = 0; pi < 2; pi++) {
        int pair = w + pi * 8;
        int i = pair & 7, m = pair >> 3;
        float vals[8];
        float ss = 0.f;
        #pragma unroll
        for (int q = 0; q < 8; q++) {
            int e = lane + 32 * q;
            float rv = s_rep[i][e];
            float sg = (rv > 0.f ? 1.f : 0.f) - (rv < 0.f ? 1.f : 0.f);
            float v = (s_off[i][m * 256 + e] + fabsf(rv)) * sg;
            vals[q] = v;
            ss += v * v;
        }
        #pragma unroll
        for (int off = 16; off > 0; off >>= 1) ss += __shfl_xor_sync(0xffffffffu, ss, off);
        float inv = 1.f / fmaxf(sqrtf(ss), 1e-12f);
        int r = r0 + i;
        int t = r >> 5, rl = r & 31;
        size_t rowb = ((size_t)(t * NCOLS + (1 + m) * 32 + rl)) * KSEG;
        #pragma unroll
        for (int q = 0; q < 8; q++) {
            int e = lane + 32 * q;
            __half hb = __float2half(vals[q] * inv);
            g_B[rowb + e]       = hb;
            g_B[rowb + 256 + e] = hb;
        }
    }
    #pragma unroll
    for (int i = 0; i < 8; i++) {
        int r = r0 + i;
        int t = r >> 5, rl = r & 31;
        __half hb = __float2half(s_rep[i][tid]);
        size_t rowb = ((size_t)(t * NCOLS + rl)) * KSEG + tid;
        g_B[rowb]       = hb;
        g_B[rowb + 256] = hb;
    }
}

// =====================================================================
// Kernel 2: conv via mma.sync fp16. C[px(128)][e(256)], K=512.
// 512 threads, 16 warps (4m x 4n). Double-buffered, register prefetch.
// =====================================================================
#define CV_SA(buf) ((buf) ? 16384 : 0)
#define CV_SB(buf) (32768 + ((buf) ? 32768 : 0))
#define CV_CST 257
#define CV_PSUM (131584)
#define CV_SBIAS (131584 + 2048)
#define CV_SMEM (131584 + 2048 + 1024)     // 134656

__global__ __launch_bounds__(512) void conv_mma_kernel(
    const float* __restrict__ W,
    const float* __restrict__ bias)
{
    extern __shared__ char smem[];
    const uint32_t sbase = smem_u32(smem);
    const int tid = threadIdx.x;
    const int lane = tid & 31;
    const int wid = tid >> 5;
    const int warp_m = wid & 3;
    const int warp_n = wid >> 2;
    const int p0 = blockIdx.x * MPX;

    if (tid < 256) ((float*)(smem + CV_SBIAS))[tid] = bias[tid];

    float acc[2][8][4];
    #pragma unroll
    for (int mt = 0; mt < 2; mt++)
        #pragma unroll
        for (int j = 0; j < 8; j++)
            #pragma unroll
            for (int q = 0; q < 4; q++) acc[mt][j][q] = 0.f;

    uint4 va[2];
    uint2 vw[8];
    {
        #pragma unroll
        for (int i = 0; i < 2; i++) {
            int idx = tid + 512 * i, row = idx >> 3, c = idx & 7;
            va[i] = *(const uint4*)&g_xth[(size_t)(p0 + row) * KSEG + c * 8];
        }
        #pragma unroll
        for (int i = 0; i < 8; i++) {
            int idx = tid + 512 * i, row = idx >> 4, c4 = idx & 15;
            float4 v = *(const float4*)&W[(size_t)row * 256 + c4 * 4];
            vw[i] = cvt_f4h(v, false);
        }
    }

    for (int s = 0; s < NCHUNK; s++) {
        const int buf = s & 1;
        char* sa = smem + CV_SA(buf);
        char* sb = smem + CV_SB(buf);
        #pragma unroll
        for (int i = 0; i < 2; i++) {
            int idx = tid + 512 * i, row = idx >> 3, c = idx & 7;
            *(uint4*)(sa + (((row << 3) + (c ^ (row & 7))) << 4)) = va[i];
        }
        #pragma unroll
        for (int i = 0; i < 8; i++) {
            int idx = tid + 512 * i, row = idx >> 4, c4 = idx & 15;
            int g = c4 >> 1, half = c4 & 1;
            *(uint2*)(sb + (row << 7) + ((g ^ (row & 7)) << 4) + (half << 3)) = vw[i];
        }
        __syncthreads();

        if (s < NCHUNK - 1) {
            const int sn = s + 1;
            const int c0n = (sn & 3) << 6;
            #pragma unroll
            for (int i = 0; i < 2; i++) {
                int idx = tid + 512 * i, row = idx >> 3, c = idx & 7;
                va[i] = *(const uint4*)&g_xth[(size_t)(p0 + row) * KSEG + sn * 64 + c * 8];
            }
            #pragma unroll
            for (int i = 0; i < 8; i++) {
                int idx = tid + 512 * i, row = idx >> 4, c4 = idx & 15;
                float4 v = *(const float4*)&W[(size_t)row * 256 + c0n + c4 * 4];
                vw[i] = cvt_f4h(v, false);
            }
        }

        const uint32_t saA = sbase + CV_SA(buf);
        const uint32_t saB = sbase + CV_SB(buf);
        #pragma unroll
        for (int kk = 0; kk < 4; kk++) {
            uint32_t af[2][4];
            #pragma unroll
            for (int mt = 0; mt < 2; mt++) {
                int row = warp_m * 32 + mt * 16 + (lane & 15);
                int c = kk * 2 + (lane >> 4);
                uint32_t addr = saA + (((row << 3) + (c ^ (row & 7))) << 4);
                LDSM_X4(af[mt][0], af[mt][1], af[mt][2], af[mt][3], addr);
            }
            uint32_t bf[4][4];
            #pragma unroll
            for (int bp = 0; bp < 4; bp++) {
                int row = warp_n * 64 + bp * 16 + ((lane >> 4) << 3) + (lane & 7);
                int c = kk * 2 + ((lane >> 3) & 1);
                uint32_t addr = saB + (((row << 3) + (c ^ (row & 7))) << 4);
                LDSM_X4(bf[bp][0], bf[bp][1], bf[bp][2], bf[bp][3], addr);
            }
            #pragma unroll
            for (int mt = 0; mt < 2; mt++) {
                #pragma unroll
                for (int bp = 0; bp < 4; bp++) {
                    MMA_F16(acc[mt][bp * 2 + 0], af[mt], bf[bp][0], bf[bp][1]);
                    MMA_F16(acc[mt][bp * 2 + 1], af[mt], bf[bp][2], bf[bp][3]);
                }
            }
        }
        __syncthreads();
    }

    // stage C (+bias) to smem: Cf[px][e]
    float* Cf = (float*)smem;
    const float* sbias = (const float*)(smem + CV_SBIAS);
    #pragma unroll
    for (int mt = 0; mt < 2; mt++) {
        #pragma unroll
        for (int j = 0; j < 8; j++) {
            int row = warp_m * 32 + mt * 16 + (lane >> 2);
            int col = warp_n * 64 + j * 8 + 2 * (lane & 3);
            Cf[row * CV_CST + col]           = acc[mt][j][0] + sbias[col];
            Cf[row * CV_CST + col + 1]       = acc[mt][j][1] + sbias[col + 1];
            Cf[(row + 8) * CV_CST + col]     = acc[mt][j][2] + sbias[col];
            Cf[(row + 8) * CV_CST + col + 1] = acc[mt][j][3] + sbias[col + 1];
        }
    }
    __syncthreads();

    // norm over e
    const int px = tid & 127;
    const int q = tid >> 7;
    float* psum = (float*)(smem + CV_PSUM);
    {
        float s = 0.f;
        #pragma unroll 8
        for (int e = q * 64; e < q * 64 + 64; e++) {
            float v = Cf[px * CV_CST + e];
            s += v * v;
        }
        psum[q * 128 + px] = s;
    }
    __syncthreads();
    {
        float tot = psum[px] + psum[128 + px] + psum[256 + px] + psum[384 + px];
        float inv = 1.f / fmaxf(sqrtf(tot), 1e-12f);
        size_t rowb = (size_t)(p0 + px) * KSEG;
        #pragma unroll
        for (int g = 0; g < 8; g++) {
            int e = q * 64 + g * 8;
            uint32_t ph[4], pl[4];
            #pragma unroll
            for (int j = 0; j < 4; j++) {
                float f0 = Cf[px * CV_CST + e + 2 * j]     * inv;
                float f1 = Cf[px * CV_CST + e + 2 * j + 1] * inv;
                __half h0 = __float2half(f0);
                __half h1 = __float2half(f1);
                ph[j] = pk_hf2(h0, h1);
                pl[j] = pk_hf2(__float2half(f0 - __half2float(h0)),
                               __float2half(f1 - __half2float(h1)));
            }
            *(uint4*)&g_embA[rowb + e]       = *(uint4*)ph;
            *(uint4*)&g_embA[rowb + 256 + e] = *(uint4*)pl;
        }
    }
}

// =====================================================================
// Kernel 3: main fp16 mma.sync GEMM (128px x 96col, K=512) + epilogue.
// 256 threads, 8 warps (4m x 2n), warp tile 32x48. Streaming stores.
// =====================================================================
#define SMA(buf) ((buf) ? 16384 : 0)
#define SMB(buf) (32768 + ((buf) ? 12288 : 0))
#define CSTRIDE 129
#define SUMBUF_OFF 49536
#define SMEM_TOT 57344

__global__ __launch_bounds__(256) void dml_main_kernel(float* __restrict__ out)
{
    extern __shared__ char smem[];
    const uint32_t sbase = smem_u32(smem);
    const int tid = threadIdx.x;
    const int lane = tid & 31;
    const int wid = tid >> 5;
    const int warp_m = wid & 3;
    const int warp_n = wid >> 2;
    const int p0 = (int)blockIdx.x * MPX;
    const int rt = (int)blockIdx.y;
    const int r1 = rt * NT_R;
    const int bimg = p0 >> 12;
    const int hw0 = p0 & 4095;

    const __half* abase = g_embA + (size_t)p0 * KSEG;
    const __half* bbase = g_B + (size_t)rt * NCOLS * KSEG;

    float acc[2][6][4];
    #pragma unroll
    for (int mt = 0; mt < 2; mt++)
        #pragma unroll
        for (int j = 0; j < 6; j++)
            #pragma unroll
            for (int q = 0; q < 4; q++) acc[mt][j][q] = 0.f;

    uint4 va[4], vb[3];
    #pragma unroll
    for (int i = 0; i < 4; i++) {
        int idx = tid + 256 * i, row = idx >> 3, c = idx & 7;
        va[i] = *((const uint4*)(abase + (size_t)row * KSEG) + c);
    }
    #pragma unroll
    for (int i = 0; i < 3; i++) {
        int idx = tid + 256 * i, row = idx >> 3, c = idx & 7;
        vb[i] = *((const uint4*)(bbase + (size_t)row * KSEG) + c);
    }

    for (int s = 0; s < NCHUNK; s++) {
        const int buf = s & 1;
        char* sa = smem + SMA(buf);
        char* sb = smem + SMB(buf);
        #pragma unroll
        for (int i = 0; i < 4; i++) {
            int idx = tid + 256 * i, row = idx >> 3, c = idx & 7;
            *(uint4*)(sa + (((row << 3) + (c ^ (row & 7))) << 4)) = va[i];
        }
        #pragma unroll
        for (int i = 0; i < 3; i++) {
            int idx = tid + 256 * i, row = idx >> 3, c = idx & 7;
            *(uint4*)(sb + (((row << 3) + (c ^ (row & 7))) << 4)) = vb[i];
        }
        __syncthreads();

        if (s < NCHUNK - 1) {
            const int k0 = (s + 1) * 64;
            #pragma unroll
            for (int i = 0; i < 4; i++) {
                int idx = tid + 256 * i, row = idx >> 3, c = idx & 7;
                va[i] = *((const uint4*)(abase + (size_t)row * KSEG + k0) + c);
            }
            #pragma unroll
            for (int i = 0; i < 3; i++) {
                int idx = tid + 256 * i, row = idx >> 3, c = idx & 7;
                vb[i] = *((const uint4*)(bbase + (size_t)row * KSEG + k0) + c);
            }
        }

        const uint32_t saA = sbase + SMA(buf);
        const uint32_t saB = sbase + SMB(buf);
        #pragma unroll
        for (int kk = 0; kk < 4; kk++) {
            uint32_t af[2][4];
            #pragma unroll
            for (int mt = 0; mt < 2; mt++) {
                int row = warp_m * 32 + mt * 16 + (lane & 15);
                int c = kk * 2 + (lane >> 4);
                uint32_t addr = saA + (((row << 3) + (c ^ (row & 7))) << 4);
                LDSM_X4(af[mt][0], af[mt][1], af[mt][2], af[mt][3], addr);
            }
            uint32_t bf[3][4];
            #pragma unroll
            for (int bp = 0; bp < 3; bp++) {
                int row = warp_n * 48 + bp * 16 + ((lane >> 4) << 3) + (lane & 7);
                int c = kk * 2 + ((lane >> 3) & 1);
                uint32_t addr = saB + (((row << 3) + (c ^ (row & 7))) << 4);
                LDSM_X4(bf[bp][0], bf[bp][1], bf[bp][2], bf[bp][3], addr);
            }
            #pragma unroll
            for (int mt = 0; mt < 2; mt++) {
                #pragma unroll
                for (int bp = 0; bp < 3; bp++) {
                    MMA_F16(acc[mt][bp * 2 + 0], af[mt], bf[bp][0], bf[bp][1]);
                    MMA_F16(acc[mt][bp * 2 + 1], af[mt], bf[bp][2], bf[bp][3]);
                }
            }
        }
        __syncthreads();
    }

    // stage C to smem
    float* Cf = (float*)smem;
    #pragma unroll
    for (int mt = 0; mt < 2; mt++) {
        #pragma unroll
        for (int j = 0; j < 6; j++) {
            int row = warp_m * 32 + mt * 16 + (lane >> 2);
            int col = warp_n * 48 + j * 8 + 2 * (lane & 3);
            Cf[col * CSTRIDE + row]           = acc[mt][j][0];
            Cf[(col + 1) * CSTRIDE + row]     = acc[mt][j][1];
            Cf[col * CSTRIDE + row + 8]       = acc[mt][j][2];
            Cf[(col + 1) * CSTRIDE + row + 8] = acc[mt][j][3];
        }
    }
    __syncthreads();

    // epilogue (streaming stores)
    const int px = tid & 127;
    const int rg = tid >> 7;
    const int hw = hw0 + px;
    const size_t oimg = (size_t)bimg * RNUM;
    float ssum = 0.f;

    #pragma unroll
    for (int pass = 0; pass < 16; pass++) {
        int rloc = pass * 2 + rg;
        int r = r1 + rloc;
        if (r < RNUM) {
            float dp = Cf[rloc * CSTRIDE + px];
            float d0 = Cf[(32 + rloc) * CSTRIDE + px];
            float d1 = Cf[(64 + rloc) * CSTRIDE + px];
            float dp2 = fmaxf(2.f - 2.f * dp, 0.f);
            float d02 = fmaxf(2.f - 2.f * d0, 0.f);
            float d12 = fmaxf(2.f - 2.f * d1, 0.f);
            float dmin2 = fminf(d02, d12);
            float dpl = dp2 * rsqrtf(fmaxf(dp2, 1e-30f));
            float d0l = d02 * rsqrtf(fmaxf(d02, 1e-30f));
            float d1l = d12 * rsqrtf(fmaxf(d12, 1e-30f));
            float dminl = fminf(d0l, d1l);
            float fcn = __expf(-2.f * dmin2);
            float fpo = __expf(-2.f * dp2);
            float tt = dpl + 0.3f * (2.f - dminl);
            float fpr = __expf(-2.f * tt * tt);

            size_t base = (oimg + r) * HWSZ + hw;
            STG_CS(out + OFF_DIST + base,   dpl);
            STG_CS(out + OFF_CLS + base,    fpr);
            STG_CS(out + OFF_CLSNEG + base, fcn);
            STG_CS(out + OFF_PORI + base,   fpo);
            size_t bn = (oimg + r) * 2 * HWSZ + hw;
            STG_CS(out + OFF_DNEG + bn,        d0l);
            STG_CS(out + OFF_DNEG + bn + HWSZ, d1l);
            ssum += fpr;
        }
    }

    __syncthreads();
    float* sumbuf = (float*)(smem + SUMBUF_OFF);
    sumbuf[tid] = ssum;
    __syncthreads();
    if (tid < 128)
        g_part[rt][p0 + tid] = sumbuf[tid] + sumbuf[tid + 128];
}

// =====================================================================
// Kernel 4: combine partials -> 1/sum
// =====================================================================
__global__ __launch_bounds__(256) void inv_sum_kernel()
{
    int i = blockIdx.x * 256 + threadIdx.x;
    float s = 0.f;
    #pragma unroll
    for (int t = 0; t < NTILES; t++) s += g_part[t][i];
    g_sum[i] = 1.f / s;
}

// =====================================================================
// Kernel 5: cls_score *= 1/sum
// =====================================================================
__global__ __launch_bounds__(256) void scale_cls_kernel(float* __restrict__ out)
{
    int row = blockIdx.y;
    int b = row / RNUM;
    int hw = blockIdx.x * 1024 + threadIdx.x * 4;
    float4 s = *(float4*)&g_sum[b * 4096 + hw];
    float4 v = *(float4*)&out[OFF_CLS + (size_t)row * HWSZ + hw];
    v.x *= s.x; v.y *= s.y; v.z *= s.z; v.w *= s.w;
    *(float4*)&out[OFF_CLS + (size_t)row * HWSZ + hw] = v;
}

// =====================================================================
extern "C" void kernel_launch(void* const* d_in, const int* in_sizes, int n_in,
                              void* d_out, int out_size)
{
    (void)in_sizes; (void)n_in; (void)out_size;
    const float* x      = (const float*)d_in[0];
    const float* conv_w = (const float*)d_in[1];
    const float* conv_b = (const float*)d_in[2];
    const float* reps   = (const float*)d_in[3];
    const float* neg_w  = (const float*)d_in[4];
    const float* neg_b  = (const float*)d_in[5];
    float* out = (float*)d_out;

    cudaFuncSetAttribute(dml_main_kernel,
                         cudaFuncAttributeMaxDynamicSharedMemorySize, SMEM_TOT);
    cudaFuncSetAttribute(conv_mma_kernel,
                         cudaFuncAttributeMaxDynamicSharedMemorySize, CV_SMEM);

    transpose_kernel<<<dim3(128, 8, 16), 256>>>(x);
    prep_reps_kernel<<<48, 256>>>(reps, neg_w, neg_b);
    conv_mma_kernel<<<512, 512, CV_SMEM>>>(conv_w, conv_b);
    dml_main_kernel<<<dim3(512, NTILES), 256, SMEM_TOT>>>(out);
    inv_sum_kernel<<<256, 256>>>();
    scale_cls_kernel<<<dim3(4, BATCH * RNUM), 256>>>(out);
}

// round 10
// speedup vs baseline: 1.5472x; 1.5472x over previous
#include <cuda_runtime.h>
#include <cuda_fp16.h>
#include <cstdint>
#include <math.h>

// ---------------- problem constants ----------------
#define BATCH 16
#define EDIM  256
#define HWSZ  4096
#define NPIX  65536
#define RNUM  365
#define KSEG  512            // fp16 split-2: A'=[hi|lo], B'=[hi|hi]
#define NT_R  32
#define NCOLS 96             // 3 modes * 32 r
#define NTILES 12
#define MPX   128
#define NCHUNK 8             // 512 / 64

#define TOT1     ((size_t)BATCH * RNUM * HWSZ)
#define OFF_CLS    ((size_t)0)
#define OFF_CLSNEG (TOT1)
#define OFF_DIST   (2*TOT1)
#define OFF_DNEG   (3*TOT1)
#define OFF_PORI   (5*TOT1)

// ---------------- static device scratch ----------------
__device__ __half g_xth[(size_t)NPIX * KSEG];              // 64 MB  x transposed, fp16 [hi|lo]
__device__ __half g_embA[(size_t)NPIX * KSEG];             // 64 MB  emb split [hi|lo]
__device__ __half g_B[(size_t)NTILES * NCOLS * KSEG];      // 1.2 MB reps [hi|hi]
__device__ float g_part[NTILES][NPIX];
__device__ float g_sum[NPIX];

// ---------------- helpers ----------------
__device__ __forceinline__ uint32_t pk_hf2(__half a, __half b) {
    unsigned short ua = __half_as_ushort(a), ub = __half_as_ushort(b);
    return (uint32_t)ua | ((uint32_t)ub << 16);
}
__device__ __forceinline__ uint32_t smem_u32(const void* p) {
    uint32_t a;
    asm("{ .reg .u64 t; cvta.to.shared.u64 t, %1; cvt.u32.u64 %0, t; }" : "=r"(a) : "l"(p));
    return a;
}
__device__ __forceinline__ uint2 cvt_f4h(float4 v, bool lo) {
    __half h0 = __float2half(v.x), h1 = __float2half(v.y),
           h2 = __float2half(v.z), h3 = __float2half(v.w);
    if (lo) {
        h0 = __float2half(v.x - __half2float(h0));
        h1 = __float2half(v.y - __half2float(h1));
        h2 = __float2half(v.z - __half2float(h2));
        h3 = __float2half(v.w - __half2float(h3));
    }
    uint2 r; r.x = pk_hf2(h0, h1); r.y = pk_hf2(h2, h3); return r;
}

#define LDSM_X4(r0, r1, r2, r3, addr)                                          \
    asm volatile("ldmatrix.sync.aligned.m8n8.x4.shared.b16 {%0,%1,%2,%3}, [%4];" \
        : "=r"(r0), "=r"(r1), "=r"(r2), "=r"(r3) : "r"(addr))

#define MMA_F16(c, a, b0, b1)                                                  \
    asm volatile("mma.sync.aligned.m16n8k16.row.col.f32.f16.f16.f32 "          \
        "{%0,%1,%2,%3}, {%4,%5,%6,%7}, {%8,%9}, {%0,%1,%2,%3};"                \
        : "+f"((c)[0]), "+f"((c)[1]), "+f"((c)[2]), "+f"((c)[3])               \
        : "r"((a)[0]), "r"((a)[1]), "r"((a)[2]), "r"((a)[3]), "r"(b0), "r"(b1))

#define CP_ASYNC16(smem_addr, gptr)                                            \
    asm volatile("cp.async.cg.shared.global [%0], [%1], 16;"                   \
        :: "r"(smem_addr), "l"(gptr))
#define CP_COMMIT() asm volatile("cp.async.commit_group;" ::: "memory")
#define CP_WAIT1()  asm volatile("cp.async.wait_group 1;" ::: "memory")
#define CP_WAIT0()  asm volatile("cp.async.wait_group 0;" ::: "memory")

// =====================================================================
// Kernel 0: transpose x[b][c][hw] -> g_xth[b*4096+hw][c] fp16 [hi|lo]
// =====================================================================
__global__ __launch_bounds__(256) void transpose_kernel(const float* __restrict__ x)
{
    __shared__ float tl[32][33];
    const int hw0 = blockIdx.x * 32, c0 = blockIdx.y * 32, b = blockIdx.z;
    const int tx = threadIdx.x & 31, ty = threadIdx.x >> 5;
    const float* src = x + ((size_t)b * 256 + c0) * 4096 + hw0;
    #pragma unroll
    for (int j = 0; j < 4; j++)
        tl[ty * 4 + j][tx] = src[(size_t)(ty * 4 + j) * 4096 + tx];
    __syncthreads();
    #pragma unroll
    for (int j = 0; j < 4; j++) {
        float v = tl[tx][ty * 4 + j];
        __half hi = __float2half(v);
        __half lo = __float2half(v - __half2float(hi));
        size_t rowb = ((size_t)b * 4096 + hw0 + ty * 4 + j) * KSEG + c0 + tx;
        g_xth[rowb]       = hi;
        g_xth[rowb + 256] = lo;
    }
}

// =====================================================================
// Kernel 1: build B' (pos / neg0 / neg1, normalized, fp16 [hi|hi]).
// B layout: [tile(12)][col(96) = mode*32 + (r&31)][KSEG]
// =====================================================================
__global__ __launch_bounds__(256) void prep_reps_kernel(
    const float* __restrict__ reps,
    const float* __restrict__ negw,
    const float* __restrict__ negb)
{
    __shared__ float s_rep[8][256];
    __shared__ float s_off[8][512];
    const int tid = threadIdx.x;
    const int r0 = blockIdx.x * 8;
    const int w = tid >> 5, lane = tid & 31;

    #pragma unroll
    for (int i = 0; i < 8; i++) {
        int r = r0 + i;
        s_rep[i][tid] = (r < RNUM) ? reps[r * 256 + tid] : 0.f;
    }
    __syncthreads();

    for (int jj = 0; jj < 64; jj++) {
        int j = w * 64 + jj;
        float part[8];
        #pragma unroll
        for (int rl = 0; rl < 8; rl++) part[rl] = 0.f;
        #pragma unroll
        for (int i2 = 0; i2 < 8; i2++) {
            int k = lane + 32 * i2;
            float wv = negw[j * 256 + k];
            #pragma unroll
            for (int rl = 0; rl < 8; rl++) part[rl] += wv * fabsf(s_rep[rl][k]);
        }
        #pragma unroll
        for (int off = 16; off > 0; off >>= 1) {
            #pragma unroll
            for (int rl = 0; rl < 8; rl++)
                part[rl] += __shfl_xor_sync(0xffffffffu, part[rl], off);
        }
        if (lane < 8) s_off[lane][j] = part[lane] + negb[j];
    }
    __syncthreads();

    #pragma unroll
    for (int pi = 0; pi < 2; pi++) {
        int pair = w + pi * 8;
        int i = pair & 7, m = pair >> 3;
        float vals[8];
        float ss = 0.f;
        #pragma unroll
        for (int q = 0; q < 8; q++) {
            int e = lane + 32 * q;
            float rv = s_rep[i][e];
            float sg = (rv > 0.f ? 1.f : 0.f) - (rv < 0.f ? 1.f : 0.f);
            float v = (s_off[i][m * 256 + e] + fabsf(rv)) * sg;
            vals[q] = v;
            ss += v * v;
        }
        #pragma unroll
        for (int off = 16; off > 0; off >>= 1) ss += __shfl_xor_sync(0xffffffffu, ss, off);
        float inv = 1.f / fmaxf(sqrtf(ss), 1e-12f);
        int r = r0 + i;
        int t = r >> 5, rl = r & 31;
        size_t rowb = ((size_t)(t * NCOLS + (1 + m) * 32 + rl)) * KSEG;
        #pragma unroll
        for (int q = 0; q < 8; q++) {
            int e = lane + 32 * q;
            __half hb = __float2half(vals[q] * inv);
            g_B[rowb + e]       = hb;
            g_B[rowb + 256 + e] = hb;
        }
    }
    #pragma unroll
    for (int i = 0; i < 8; i++) {
        int r = r0 + i;
        int t = r >> 5, rl = r & 31;
        __half hb = __float2half(s_rep[i][tid]);
        size_t rowb = ((size_t)(t * NCOLS + rl)) * KSEG + tid;
        g_B[rowb]       = hb;
        g_B[rowb + 256] = hb;
    }
}

// =====================================================================
// Kernel 2: conv via mma.sync fp16. C[px(128)][e(256)], K=512.
// 512 threads, 16 warps (4m x 4n). Double-buffered, register prefetch.
// =====================================================================
#define CV_SA(buf) ((buf) ? 16384 : 0)
#define CV_SB(buf) (32768 + ((buf) ? 32768 : 0))
#define CV_CST 257
#define CV_PSUM (131584)
#define CV_SBIAS (131584 + 2048)
#define CV_SMEM (131584 + 2048 + 1024)     // 134656

__global__ __launch_bounds__(512) void conv_mma_kernel(
    const float* __restrict__ W,
    const float* __restrict__ bias)
{
    extern __shared__ char smem[];
    const uint32_t sbase = smem_u32(smem);
    const int tid = threadIdx.x;
    const int lane = tid & 31;
    const int wid = tid >> 5;
    const int warp_m = wid & 3;
    const int warp_n = wid >> 2;
    const int p0 = blockIdx.x * MPX;

    if (tid < 256) ((float*)(smem + CV_SBIAS))[tid] = bias[tid];

    float acc[2][8][4];
    #pragma unroll
    for (int mt = 0; mt < 2; mt++)
        #pragma unroll
        for (int j = 0; j < 8; j++)
            #pragma unroll
            for (int q = 0; q < 4; q++) acc[mt][j][q] = 0.f;

    uint4 va[2];
    uint2 vw[8];
    {
        #pragma unroll
        for (int i = 0; i < 2; i++) {
            int idx = tid + 512 * i, row = idx >> 3, c = idx & 7;
            va[i] = *(const uint4*)&g_xth[(size_t)(p0 + row) * KSEG + c * 8];
        }
        #pragma unroll
        for (int i = 0; i < 8; i++) {
            int idx = tid + 512 * i, row = idx >> 4, c4 = idx & 15;
            float4 v = *(const float4*)&W[(size_t)row * 256 + c4 * 4];
            vw[i] = cvt_f4h(v, false);
        }
    }

    for (int s = 0; s < NCHUNK; s++) {
        const int buf = s & 1;
        char* sa = smem + CV_SA(buf);
        char* sb = smem + CV_SB(buf);
        #pragma unroll
        for (int i = 0; i < 2; i++) {
            int idx = tid + 512 * i, row = idx >> 3, c = idx & 7;
            *(uint4*)(sa + (((row << 3) + (c ^ (row & 7))) << 4)) = va[i];
        }
        #pragma unroll
        for (int i = 0; i < 8; i++) {
            int idx = tid + 512 * i, row = idx >> 4, c4 = idx & 15;
            int g = c4 >> 1, half = c4 & 1;
            *(uint2*)(sb + (row << 7) + ((g ^ (row & 7)) << 4) + (half << 3)) = vw[i];
        }
        __syncthreads();

        if (s < NCHUNK - 1) {
            const int sn = s + 1;
            const int c0n = (sn & 3) << 6;
            #pragma unroll
            for (int i = 0; i < 2; i++) {
                int idx = tid + 512 * i, row = idx >> 3, c = idx & 7;
                va[i] = *(const uint4*)&g_xth[(size_t)(p0 + row) * KSEG + sn * 64 + c * 8];
            }
            #pragma unroll
            for (int i = 0; i < 8; i++) {
                int idx = tid + 512 * i, row = idx >> 4, c4 = idx & 15;
                float4 v = *(const float4*)&W[(size_t)row * 256 + c0n + c4 * 4];
                vw[i] = cvt_f4h(v, false);
            }
        }

        const uint32_t saA = sbase + CV_SA(buf);
        const uint32_t saB = sbase + CV_SB(buf);
        #pragma unroll
        for (int kk = 0; kk < 4; kk++) {
            uint32_t af[2][4];
            #pragma unroll
            for (int mt = 0; mt < 2; mt++) {
                int row = warp_m * 32 + mt * 16 + (lane & 15);
                int c = kk * 2 + (lane >> 4);
                uint32_t addr = saA + (((row << 3) + (c ^ (row & 7))) << 4);
                LDSM_X4(af[mt][0], af[mt][1], af[mt][2], af[mt][3], addr);
            }
            uint32_t bf[4][4];
            #pragma unroll
            for (int bp = 0; bp < 4; bp++) {
                int row = warp_n * 64 + bp * 16 + ((lane >> 4) << 3) + (lane & 7);
                int c = kk * 2 + ((lane >> 3) & 1);
                uint32_t addr = saB + (((row << 3) + (c ^ (row & 7))) << 4);
                LDSM_X4(bf[bp][0], bf[bp][1], bf[bp][2], bf[bp][3], addr);
            }
            #pragma unroll
            for (int mt = 0; mt < 2; mt++) {
                #pragma unroll
                for (int bp = 0; bp < 4; bp++) {
                    MMA_F16(acc[mt][bp * 2 + 0], af[mt], bf[bp][0], bf[bp][1]);
                    MMA_F16(acc[mt][bp * 2 + 1], af[mt], bf[bp][2], bf[bp][3]);
                }
            }
        }
        __syncthreads();
    }

    // stage C (+bias) to smem: Cf[px][e]
    float* Cf = (float*)smem;
    const float* sbias = (const float*)(smem + CV_SBIAS);
    #pragma unroll
    for (int mt = 0; mt < 2; mt++) {
        #pragma unroll
        for (int j = 0; j < 8; j++) {
            int row = warp_m * 32 + mt * 16 + (lane >> 2);
            int col = warp_n * 64 + j * 8 + 2 * (lane & 3);
            Cf[row * CV_CST + col]           = acc[mt][j][0] + sbias[col];
            Cf[row * CV_CST + col + 1]       = acc[mt][j][1] + sbias[col + 1];
            Cf[(row + 8) * CV_CST + col]     = acc[mt][j][2] + sbias[col];
            Cf[(row + 8) * CV_CST + col + 1] = acc[mt][j][3] + sbias[col + 1];
        }
    }
    __syncthreads();

    // norm over e
    const int px = tid & 127;
    const int q = tid >> 7;
    float* psum = (float*)(smem + CV_PSUM);
    {
        float s = 0.f;
        #pragma unroll 8
        for (int e = q * 64; e < q * 64 + 64; e++) {
            float v = Cf[px * CV_CST + e];
            s += v * v;
        }
        psum[q * 128 + px] = s;
    }
    __syncthreads();
    {
        float tot = psum[px] + psum[128 + px] + psum[256 + px] + psum[384 + px];
        float inv = 1.f / fmaxf(sqrtf(tot), 1e-12f);
        size_t rowb = (size_t)(p0 + px) * KSEG;
        #pragma unroll
        for (int g = 0; g < 8; g++) {
            int e = q * 64 + g * 8;
            uint32_t ph[4], pl[4];
            #pragma unroll
            for (int j = 0; j < 4; j++) {
                float f0 = Cf[px * CV_CST + e + 2 * j]     * inv;
                float f1 = Cf[px * CV_CST + e + 2 * j + 1] * inv;
                __half h0 = __float2half(f0);
                __half h1 = __float2half(f1);
                ph[j] = pk_hf2(h0, h1);
                pl[j] = pk_hf2(__float2half(f0 - __half2float(h0)),
                               __float2half(f1 - __half2float(h1)));
            }
            *(uint4*)&g_embA[rowb + e]       = *(uint4*)ph;
            *(uint4*)&g_embA[rowb + 256 + e] = *(uint4*)pl;
        }
    }
}

// =====================================================================
// Kernel 3: main fp16 mma.sync GEMM (128px x 96col, K=512) + epilogue.
// 256 threads, 8 warps (4m x 2n), warp tile 32x48. cp.async double-buffer.
// =====================================================================
#define SMA(buf) ((buf) ? 16384 : 0)
#define SMB(buf) (32768 + ((buf) ? 12288 : 0))
#define CSTRIDE 129
#define SUMBUF_OFF 49536
#define SMEM_TOT 57344

__global__ __launch_bounds__(256) void dml_main_kernel(float* __restrict__ out)
{
    extern __shared__ char smem[];
    const uint32_t sbase = smem_u32(smem);
    const int tid = threadIdx.x;
    const int lane = tid & 31;
    const int wid = tid >> 5;
    const int warp_m = wid & 3;
    const int warp_n = wid >> 2;
    const int p0 = (int)blockIdx.x * MPX;
    const int rt = (int)blockIdx.y;
    const int r1 = rt * NT_R;
    const int bimg = p0 >> 12;
    const int hw0 = p0 & 4095;

    const __half* abase = g_embA + (size_t)p0 * KSEG;
    const __half* bbase = g_B + (size_t)rt * NCOLS * KSEG;

    float acc[2][6][4];
    #pragma unroll
    for (int mt = 0; mt < 2; mt++)
        #pragma unroll
        for (int j = 0; j < 6; j++)
            #pragma unroll
            for (int q = 0; q < 4; q++) acc[mt][j][q] = 0.f;

    // cp.async: A 128x64 (16KB) -> 4 x 16B/thread; B 96x64 (12KB) -> 3 x 16B/thread
    auto issue_chunk = [&](int s) {
        const int buf = s & 1;
        const int k0 = s * 64;
        const uint32_t sa = sbase + SMA(buf);
        const uint32_t sb = sbase + SMB(buf);
        #pragma unroll
        for (int i = 0; i < 4; i++) {
            int idx = tid + 256 * i, row = idx >> 3, c = idx & 7;
            uint32_t dst = sa + (((row << 3) + (c ^ (row & 7))) << 4);
            CP_ASYNC16(dst, abase + (size_t)row * KSEG + k0 + c * 8);
        }
        #pragma unroll
        for (int i = 0; i < 3; i++) {
            int idx = tid + 256 * i, row = idx >> 3, c = idx & 7;
            uint32_t dst = sb + (((row << 3) + (c ^ (row & 7))) << 4);
            CP_ASYNC16(dst, bbase + (size_t)row * KSEG + k0 + c * 8);
        }
        CP_COMMIT();
    };

    issue_chunk(0);

    for (int s = 0; s < NCHUNK; s++) {
        if (s < NCHUNK - 1) { issue_chunk(s + 1); CP_WAIT1(); }
        else                { CP_WAIT0(); }
        __syncthreads();

        const int buf = s & 1;
        const uint32_t saA = sbase + SMA(buf);
        const uint32_t saB = sbase + SMB(buf);
        #pragma unroll
        for (int kk = 0; kk < 4; kk++) {
            uint32_t af[2][4];
            #pragma unroll
            for (int mt = 0; mt < 2; mt++) {
                int row = warp_m * 32 + mt * 16 + (lane & 15);
                int c = kk * 2 + (lane >> 4);
                uint32_t addr = saA + (((row << 3) + (c ^ (row & 7))) << 4);
                LDSM_X4(af[mt][0], af[mt][1], af[mt][2], af[mt][3], addr);
            }
            uint32_t bf[3][4];
            #pragma unroll
            for (int bp = 0; bp < 3; bp++) {
                int row = warp_n * 48 + bp * 16 + ((lane >> 4) << 3) + (lane & 7);
                int c = kk * 2 + ((lane >> 3) & 1);
                uint32_t addr = saB + (((row << 3) + (c ^ (row & 7))) << 4);
                LDSM_X4(bf[bp][0], bf[bp][1], bf[bp][2], bf[bp][3], addr);
            }
            #pragma unroll
            for (int mt = 0; mt < 2; mt++) {
                #pragma unroll
                for (int bp = 0; bp < 3; bp++) {
                    MMA_F16(acc[mt][bp * 2 + 0], af[mt], bf[bp][0], bf[bp][1]);
                    MMA_F16(acc[mt][bp * 2 + 1], af[mt], bf[bp][2], bf[bp][3]);
                }
            }
        }
        __syncthreads();
    }

    // stage C to smem
    float* Cf = (float*)smem;
    #pragma unroll
    for (int mt = 0; mt < 2; mt++) {
        #pragma unroll
        for (int j = 0; j < 6; j++) {
            int row = warp_m * 32 + mt * 16 + (lane >> 2);
            int col = warp_n * 48 + j * 8 + 2 * (lane & 3);
            Cf[col * CSTRIDE + row]           = acc[mt][j][0];
            Cf[(col + 1) * CSTRIDE + row]     = acc[mt][j][1];
            Cf[col * CSTRIDE + row + 8]       = acc[mt][j][2];
            Cf[(col + 1) * CSTRIDE + row + 8] = acc[mt][j][3];
        }
    }
    __syncthreads();

    // epilogue (plain stores)
    const int px = tid & 127;
    const int rg = tid >> 7;
    const int hw = hw0 + px;
    const size_t oimg = (size_t)bimg * RNUM;
    float ssum = 0.f;

    #pragma unroll
    for (int pass = 0; pass < 16; pass++) {
        int rloc = pass * 2 + rg;
        int r = r1 + rloc;
        if (r < RNUM) {
            float dp = Cf[rloc * CSTRIDE + px];
            float d0 = Cf[(32 + rloc) * CSTRIDE + px];
            float d1 = Cf[(64 + rloc) * CSTRIDE + px];
            float dp2 = fmaxf(2.f - 2.f * dp, 0.f);
            float d02 = fmaxf(2.f - 2.f * d0, 0.f);
            float d12 = fmaxf(2.f - 2.f * d1, 0.f);
            float dmin2 = fminf(d02, d12);
            float dpl = dp2 * rsqrtf(fmaxf(dp2, 1e-30f));
            float d0l = d02 * rsqrtf(fmaxf(d02, 1e-30f));
            float d1l = d12 * rsqrtf(fmaxf(d12, 1e-30f));
            float dminl = fminf(d0l, d1l);
            float fcn = __expf(-2.f * dmin2);
            float fpo = __expf(-2.f * dp2);
            float tt = dpl + 0.3f * (2.f - dminl);
            float fpr = __expf(-2.f * tt * tt);

            size_t base = (oimg + r) * HWSZ + hw;
            out[OFF_DIST + base]   = dpl;
            out[OFF_CLS + base]    = fpr;
            out[OFF_CLSNEG + base] = fcn;
            out[OFF_PORI + base]   = fpo;
            size_t bn = (oimg + r) * 2 * HWSZ + hw;
            out[OFF_DNEG + bn]        = d0l;
            out[OFF_DNEG + bn + HWSZ] = d1l;
            ssum += fpr;
        }
    }

    __syncthreads();
    float* sumbuf = (float*)(smem + SUMBUF_OFF);
    sumbuf[tid] = ssum;
    __syncthreads();
    if (tid < 128)
        g_part[rt][p0 + tid] = sumbuf[tid] + sumbuf[tid + 128];
}

// =====================================================================
// Kernel 4: combine partials -> 1/sum
// =====================================================================
__global__ __launch_bounds__(256) void inv_sum_kernel()
{
    int i = blockIdx.x * 256 + threadIdx.x;
    float s = 0.f;
    #pragma unroll
    for (int t = 0; t < NTILES; t++) s += g_part[t][i];
    g_sum[i] = 1.f / s;
}

// =====================================================================
// Kernel 5: cls_score *= 1/sum
// =====================================================================
__global__ __launch_bounds__(256) void scale_cls_kernel(float* __restrict__ out)
{
    int row = blockIdx.y;
    int b = row / RNUM;
    int hw = blockIdx.x * 1024 + threadIdx.x * 4;
    float4 s = *(float4*)&g_sum[b * 4096 + hw];
    float4 v = *(float4*)&out[OFF_CLS + (size_t)row * HWSZ + hw];
    v.x *= s.x; v.y *= s.y; v.z *= s.z; v.w *= s.w;
    *(float4*)&out[OFF_CLS + (size_t)row * HWSZ + hw] = v;
}

// =====================================================================
extern "C" void kernel_launch(void* const* d_in, const int* in_sizes, int n_in,
                              void* d_out, int out_size)
{
    (void)in_sizes; (void)n_in; (void)out_size;
    const float* x      = (const float*)d_in[0];
    const float* conv_w = (const float*)d_in[1];
    const float* conv_b = (const float*)d_in[2];
    const float* reps   = (const float*)d_in[3];
    const float* neg_w  = (const float*)d_in[4];
    const float* neg_b  = (const float*)d_in[5];
    float* out = (float*)d_out;

    cudaFuncSetAttribute(dml_main_kernel,
                         cudaFuncAttributeMaxDynamicSharedMemorySize, SMEM_TOT);
    cudaFuncSetAttribute(conv_mma_kernel,
                         cudaFuncAttributeMaxDynamicSharedMemorySize, CV_SMEM);

    transpose_kernel<<<dim3(128, 8, 16), 256>>>(x);
    prep_reps_kernel<<<48, 256>>>(reps, neg_w, neg_b);
    conv_mma_kernel<<<512, 512, CV_SMEM>>>(conv_w, conv_b);
    dml_main_kernel<<<dim3(512, NTILES), 256, SMEM_TOT>>>(out);
    inv_sum_kernel<<<256, 256>>>();
    scale_cls_kernel<<<dim3(4, BATCH * RNUM), 256>>>(out);
}

// round 12
// speedup vs baseline: 1.6668x; 1.0773x over previous
#include <cuda_runtime.h>
#include <cuda_fp16.h>
#include <cstdint>
#include <math.h>

// ---------------- problem constants ----------------
#define BATCH 16
#define EDIM  256
#define HWSZ  4096
#define NPIX  65536
#define RNUM  365
#define KSEG  512            // fp16 split-2: A'=[hi|lo], B'=[hi|hi]
#define NT_R  32
#define NCOLS 96             // 3 modes * 32 r
#define NTILES 12
#define MPX   128
#define NCHUNK 8             // 512 / 64

#define TOT1     ((size_t)BATCH * RNUM * HWSZ)
#define OFF_CLS    ((size_t)0)
#define OFF_CLSNEG (TOT1)
#define OFF_DIST   (2*TOT1)
#define OFF_DNEG   (3*TOT1)
#define OFF_PORI   (5*TOT1)

// ---------------- static device scratch ----------------
__device__ __half g_embA[(size_t)NPIX * KSEG];             // 64 MB  emb split [hi|lo]
__device__ __half g_B[(size_t)NTILES * NCOLS * KSEG];      // 1.2 MB reps [hi|hi]
__device__ float g_part[NTILES][NPIX];
__device__ float g_sum[NPIX];

// ---------------- helpers ----------------
__device__ __forceinline__ uint32_t pk_hf2(__half a, __half b) {
    unsigned short ua = __half_as_ushort(a), ub = __half_as_ushort(b);
    return (uint32_t)ua | ((uint32_t)ub << 16);
}
__device__ __forceinline__ uint32_t smem_u32(const void* p) {
    uint32_t a;
    asm("{ .reg .u64 t; cvta.to.shared.u64 t, %1; cvt.u32.u64 %0, t; }" : "=r"(a) : "l"(p));
    return a;
}
__device__ __forceinline__ uint2 cvt_f4h(float4 v, bool lo) {
    __half h0 = __float2half(v.x), h1 = __float2half(v.y),
           h2 = __float2half(v.z), h3 = __float2half(v.w);
    if (lo) {
        h0 = __float2half(v.x - __half2float(h0));
        h1 = __float2half(v.y - __half2float(h1));
        h2 = __float2half(v.z - __half2float(h2));
        h3 = __float2half(v.w - __half2float(h3));
    }
    uint2 r; r.x = pk_hf2(h0, h1); r.y = pk_hf2(h2, h3); return r;
}

#define LDSM_X4(r0, r1, r2, r3, addr)                                          \
    asm volatile("ldmatrix.sync.aligned.m8n8.x4.shared.b16 {%0,%1,%2,%3}, [%4];" \
        : "=r"(r0), "=r"(r1), "=r"(r2), "=r"(r3) : "r"(addr))

#define MMA_F16(c, a, b0, b1)                                                  \
    asm volatile("mma.sync.aligned.m16n8k16.row.col.f32.f16.f16.f32 "          \
        "{%0,%1,%2,%3}, {%4,%5,%6,%7}, {%8,%9}, {%0,%1,%2,%3};"                \
        : "+f"((c)[0]), "+f"((c)[1]), "+f"((c)[2]), "+f"((c)[3])               \
        : "r"((a)[0]), "r"((a)[1]), "r"((a)[2]), "r"((a)[3]), "r"(b0), "r"(b1))

#define CP_ASYNC16(smem_addr, gptr)                                            \
    asm volatile("cp.async.cg.shared.global [%0], [%1], 16;"                   \
        :: "r"(smem_addr), "l"(gptr))
#define CP_COMMIT() asm volatile("cp.async.commit_group;" ::: "memory")
#define CP_WAIT1()  asm volatile("cp.async.wait_group 1;" ::: "memory")
#define CP_WAIT0()  asm volatile("cp.async.wait_group 0;" ::: "memory")

// =====================================================================
// Kernel 1: build B' (pos / neg0 / neg1, normalized, fp16 [hi|hi]).
// B layout: [tile(12)][col(96) = mode*32 + (r&31)][KSEG]
// =====================================================================
__global__ __launch_bounds__(256) void prep_reps_kernel(
    const float* __restrict__ reps,
    const float* __restrict__ negw,
    const float* __restrict__ negb)
{
    __shared__ float s_rep[8][256];
    __shared__ float s_off[8][512];
    const int tid = threadIdx.x;
    const int r0 = blockIdx.x * 8;
    const int w = tid >> 5, lane = tid & 31;

    #pragma unroll
    for (int i = 0; i < 8; i++) {
        int r = r0 + i;
        s_rep[i][tid] = (r < RNUM) ? reps[r * 256 + tid] : 0.f;
    }
    __syncthreads();

    for (int jj = 0; jj < 64; jj++) {
        int j = w * 64 + jj;
        float part[8];
        #pragma unroll
        for (int rl = 0; rl < 8; rl++) part[rl] = 0.f;
        #pragma unroll
        for (int i2 = 0; i2 < 8; i2++) {
            int k = lane + 32 * i2;
            float wv = negw[j * 256 + k];
            #pragma unroll
            for (int rl = 0; rl < 8; rl++) part[rl] += wv * fabsf(s_rep[rl][k]);
        }
        #pragma unroll
        for (int off = 16; off > 0; off >>= 1) {
            #pragma unroll
            for (int rl = 0; rl < 8; rl++)
                part[rl] += __shfl_xor_sync(0xffffffffu, part[rl], off);
        }
        if (lane < 8) s_off[lane][j] = part[lane] + negb[j];
    }
    __syncthreads();

    #pragma unroll
    for (int pi = 0; pi < 2; pi++) {
        int pair = w + pi * 8;
        int i = pair & 7, m = pair >> 3;
        float vals[8];
        float ss = 0.f;
        #pragma unroll
        for (int q = 0; q < 8; q++) {
            int e = lane + 32 * q;
            float rv = s_rep[i][e];
            float sg = (rv > 0.f ? 1.f : 0.f) - (rv < 0.f ? 1.f : 0.f);
            float v = (s_off[i][m * 256 + e] + fabsf(rv)) * sg;
            vals[q] = v;
            ss += v * v;
        }
        #pragma unroll
        for (int off = 16; off > 0; off >>= 1) ss += __shfl_xor_sync(0xffffffffu, ss, off);
        float inv = 1.f / fmaxf(sqrtf(ss), 1e-12f);
        int r = r0 + i;
        int t = r >> 5, rl = r & 31;
        size_t rowb = ((size_t)(t * NCOLS + (1 + m) * 32 + rl)) * KSEG;
        #pragma unroll
        for (int q = 0; q < 8; q++) {
            int e = lane + 32 * q;
            __half hb = __float2half(vals[q] * inv);
            g_B[rowb + e]       = hb;
            g_B[rowb + 256 + e] = hb;
        }
    }
    #pragma unroll
    for (int i = 0; i < 8; i++) {
        int r = r0 + i;
        int t = r >> 5, rl = r & 31;
        __half hb = __float2half(s_rep[i][tid]);
        size_t rowb = ((size_t)(t * NCOLS + rl)) * KSEG + tid;
        g_B[rowb]       = hb;
        g_B[rowb + 256] = hb;
    }
}

// =====================================================================
// Kernel 2: fused transpose + conv. C[px(128)][e(256)].
// 512 threads, 16 warps (4m x 4n). Per c-block (4 blocks of 64 channels):
//   x tile -> scratch (cp.async, double buffered), transpose to A_hi/A_lo,
//   W tile (fp16 hi), then 2 MMA passes (hi, lo) against the same W tile.
// Epilogue: bias + L2 norm over e, write split [hi|lo] to g_embA.
// =====================================================================
#define CV_AHI 0
#define CV_ALO 16384
#define CV_W   32768
#define CV_SCR(b) (65536 + (b) * 33792)
#define CV_CST 257
#define CV_PSUM  133120
#define CV_SBIAS 135168
#define CV_SMEM  136192

__global__ __launch_bounds__(512) void conv_mma_kernel(
    const float* __restrict__ x,
    const float* __restrict__ W,
    const float* __restrict__ bias)
{
    extern __shared__ char smem[];
    const uint32_t sbase = smem_u32(smem);
    const int tid = threadIdx.x;
    const int lane = tid & 31;
    const int wid = tid >> 5;
    const int warp_m = wid & 3;
    const int warp_n = wid >> 2;
    const int p0 = blockIdx.x * MPX;
    const int bimg = p0 >> 12;
    const int hw0 = p0 & 4095;

    if (tid < 256) ((float*)(smem + CV_SBIAS))[tid] = bias[tid];

    float acc[2][8][4];
    #pragma unroll
    for (int mt = 0; mt < 2; mt++)
        #pragma unroll
        for (int j = 0; j < 8; j++)
            #pragma unroll
            for (int q = 0; q < 4; q++) acc[mt][j][q] = 0.f;

    // x scratch loader: 2048 float4 per c-block -> 4 per thread
    auto issue_x = [&](int cb) {
        const uint32_t scr = sbase + CV_SCR(cb & 1);
        #pragma unroll
        for (int i = 0; i < 4; i++) {
            int idx = tid + 512 * i;
            int cc = idx >> 5, px4 = idx & 31;
            uint32_t dst = scr + cc * 528 + px4 * 16;
            const float* src = x + ((size_t)bimg * 256 + cb * 64 + cc) * 4096 + hw0 + px4 * 4;
            CP_ASYNC16(dst, src);
        }
        CP_COMMIT();
    };

    // W register prefetch: 256x64 fp32 -> fp16 hi, 8 uint2 per thread
    uint2 vw[8];
    auto load_w = [&](int cb) {
        #pragma unroll
        for (int i = 0; i < 8; i++) {
            int idx = tid + 512 * i, row = idx >> 4, c4 = idx & 15;
            float4 v = *(const float4*)&W[(size_t)row * 256 + cb * 64 + c4 * 4];
            vw[i] = cvt_f4h(v, false);
        }
    };

    issue_x(0);
    load_w(0);

    for (int cb = 0; cb < 4; cb++) {
        // store W tile
        #pragma unroll
        for (int i = 0; i < 8; i++) {
            int idx = tid + 512 * i, row = idx >> 4, c4 = idx & 15;
            int g = c4 >> 1, half = c4 & 1;
            *(uint2*)(smem + CV_W + (row << 7) + ((g ^ (row & 7)) << 4) + (half << 3)) = vw[i];
        }
        if (cb < 3) { issue_x(cb + 1); CP_WAIT1(); }
        else        { CP_WAIT0(); }
        __syncthreads();     // scratch[cb] + W tile visible

        // build A_hi / A_lo tiles from scratch (transpose)
        {
            const float* scrf = (const float*)(smem + CV_SCR(cb & 1));
            const int px = tid & 127;
            const int grp = tid >> 7;       // 0..3 -> cc block of 16
            float xs[16];
            #pragma unroll
            for (int k = 0; k < 16; k++)
                xs[k] = scrf[(grp * 16 + k) * 132 + px];
            #pragma unroll
            for (int u = 0; u < 2; u++) {
                uint32_t ph[4], pl[4];
                #pragma unroll
                for (int j = 0; j < 4; j++) {
                    float f0 = xs[u * 8 + 2 * j], f1 = xs[u * 8 + 2 * j + 1];
                    __half h0 = __float2half(f0), h1 = __float2half(f1);
                    ph[j] = pk_hf2(h0, h1);
                    pl[j] = pk_hf2(__float2half(f0 - __half2float(h0)),
                                   __float2half(f1 - __half2float(h1)));
                }
                int c = grp * 2 + u;
                uint32_t off = (px << 7) + ((c ^ (px & 7)) << 4);
                *(uint4*)(smem + CV_AHI + off) = *(uint4*)ph;
                *(uint4*)(smem + CV_ALO + off) = *(uint4*)pl;
            }
        }
        if (cb < 3) load_w(cb + 1);
        __syncthreads();     // A tiles visible

        // MMA: reuse W fragments across hi/lo passes
        const uint32_t saW = sbase + CV_W;
        #pragma unroll
        for (int kk = 0; kk < 4; kk++) {
            uint32_t bf[4][4];
            #pragma unroll
            for (int bp = 0; bp < 4; bp++) {
                int row = warp_n * 64 + bp * 16 + ((lane >> 4) << 3) + (lane & 7);
                int c = kk * 2 + ((lane >> 3) & 1);
                uint32_t addr = saW + (((row << 3) + (c ^ (row & 7))) << 4);
                LDSM_X4(bf[bp][0], bf[bp][1], bf[bp][2], bf[bp][3], addr);
            }
            #pragma unroll
            for (int half = 0; half < 2; half++) {
                const uint32_t saA = sbase + (half ? CV_ALO : CV_AHI);
                uint32_t af[2][4];
                #pragma unroll
                for (int mt = 0; mt < 2; mt++) {
                    int row = warp_m * 32 + mt * 16 + (lane & 15);
                    int c = kk * 2 + (lane >> 4);
                    uint32_t addr = saA + (((row << 3) + (c ^ (row & 7))) << 4);
                    LDSM_X4(af[mt][0], af[mt][1], af[mt][2], af[mt][3], addr);
                }
                #pragma unroll
                for (int mt = 0; mt < 2; mt++) {
                    #pragma unroll
                    for (int bp = 0; bp < 4; bp++) {
                        MMA_F16(acc[mt][bp * 2 + 0], af[mt], bf[bp][0], bf[bp][1]);
                        MMA_F16(acc[mt][bp * 2 + 1], af[mt], bf[bp][2], bf[bp][3]);
                    }
                }
            }
        }
        __syncthreads();     // protect A/W tiles before next overwrite
    }

    // stage C (+bias) to smem: Cf[px][e]
    float* Cf = (float*)smem;
    const float* sbias = (const float*)(smem + CV_SBIAS);
    #pragma unroll
    for (int mt = 0; mt < 2; mt++) {
        #pragma unroll
        for (int j = 0; j < 8; j++) {
            int row = warp_m * 32 + mt * 16 + (lane >> 2);
            int col = warp_n * 64 + j * 8 + 2 * (lane & 3);
            Cf[row * CV_CST + col]           = acc[mt][j][0] + sbias[col];
            Cf[row * CV_CST + col + 1]       = acc[mt][j][1] + sbias[col + 1];
            Cf[(row + 8) * CV_CST + col]     = acc[mt][j][2] + sbias[col];
            Cf[(row + 8) * CV_CST + col + 1] = acc[mt][j][3] + sbias[col + 1];
        }
    }
    __syncthreads();

    // norm over e
    const int px = tid & 127;
    const int q = tid >> 7;
    float* psum = (float*)(smem + CV_PSUM);
    {
        float s = 0.f;
        #pragma unroll 8
        for (int e = q * 64; e < q * 64 + 64; e++) {
            float v = Cf[px * CV_CST + e];
            s += v * v;
        }
        psum[q * 128 + px] = s;
    }
    __syncthreads();
    {
        float tot = psum[px] + psum[128 + px] + psum[256 + px] + psum[384 + px];
        float inv = 1.f / fmaxf(sqrtf(tot), 1e-12f);
        size_t rowb = (size_t)(p0 + px) * KSEG;
        #pragma unroll
        for (int g = 0; g < 8; g++) {
            int e = q * 64 + g * 8;
            uint32_t ph[4], pl[4];
            #pragma unroll
            for (int j = 0; j < 4; j++) {
                float f0 = Cf[px * CV_CST + e + 2 * j]     * inv;
                float f1 = Cf[px * CV_CST + e + 2 * j + 1] * inv;
                __half h0 = __float2half(f0);
                __half h1 = __float2half(f1);
                ph[j] = pk_hf2(h0, h1);
                pl[j] = pk_hf2(__float2half(f0 - __half2float(h0)),
                               __float2half(f1 - __half2float(h1)));
            }
            *(uint4*)&g_embA[rowb + e]       = *(uint4*)ph;
            *(uint4*)&g_embA[rowb + 256 + e] = *(uint4*)pl;
        }
    }
}

// =====================================================================
// Kernel 3: main fp16 mma.sync GEMM (128px x 96col, K=512) + epilogue.
// 256 threads, 8 warps (4m x 2n). cp.async double-buffer.
// GRID SWAP: blockIdx.x = rt (fastest), blockIdx.y = pixel block, so the
// 12 CTAs sharing one A block are co-scheduled -> A stays in L2.
// =====================================================================
#define SMA(buf) ((buf) ? 16384 : 0)
#define SMB(buf) (32768 + ((buf) ? 12288 : 0))
#define CSTRIDE 129
#define SUMBUF_OFF 49536
#define SMEM_TOT 57344

__global__ __launch_bounds__(256) void dml_main_kernel(float* __restrict__ out)
{
    extern __shared__ char smem[];
    const uint32_t sbase = smem_u32(smem);
    const int tid = threadIdx.x;
    const int lane = tid & 31;
    const int wid = tid >> 5;
    const int warp_m = wid & 3;
    const int warp_n = wid >> 2;
    const int p0 = (int)blockIdx.y * MPX;
    const int rt = (int)blockIdx.x;
    const int r1 = rt * NT_R;
    const int bimg = p0 >> 12;
    const int hw0 = p0 & 4095;

    const __half* abase = g_embA + (size_t)p0 * KSEG;
    const __half* bbase = g_B + (size_t)rt * NCOLS * KSEG;

    float acc[2][6][4];
    #pragma unroll
    for (int mt = 0; mt < 2; mt++)
        #pragma unroll
        for (int j = 0; j < 6; j++)
            #pragma unroll
            for (int q = 0; q < 4; q++) acc[mt][j][q] = 0.f;

    auto issue_chunk = [&](int s) {
        const int buf = s & 1;
        const int k0 = s * 64;
        const uint32_t sa = sbase + SMA(buf);
        const uint32_t sb = sbase + SMB(buf);
        #pragma unroll
        for (int i = 0; i < 4; i++) {
            int idx = tid + 256 * i, row = idx >> 3, c = idx & 7;
            uint32_t dst = sa + (((row << 3) + (c ^ (row & 7))) << 4);
            CP_ASYNC16(dst, abase + (size_t)row * KSEG + k0 + c * 8);
        }
        #pragma unroll
        for (int i = 0; i < 3; i++) {
            int idx = tid + 256 * i, row = idx >> 3, c = idx & 7;
            uint32_t dst = sb + (((row << 3) + (c ^ (row & 7))) << 4);
            CP_ASYNC16(dst, bbase + (size_t)row * KSEG + k0 + c * 8);
        }
        CP_COMMIT();
    };

    issue_chunk(0);

    for (int s = 0; s < NCHUNK; s++) {
        if (s < NCHUNK - 1) { issue_chunk(s + 1); CP_WAIT1(); }
        else                { CP_WAIT0(); }
        __syncthreads();

        const int buf = s & 1;
        const uint32_t saA = sbase + SMA(buf);
        const uint32_t saB = sbase + SMB(buf);
        #pragma unroll
        for (int kk = 0; kk < 4; kk++) {
            uint32_t af[2][4];
            #pragma unroll
            for (int mt = 0; mt < 2; mt++) {
                int row = warp_m * 32 + mt * 16 + (lane & 15);
                int c = kk * 2 + (lane >> 4);
                uint32_t addr = saA + (((row << 3) + (c ^ (row & 7))) << 4);
                LDSM_X4(af[mt][0], af[mt][1], af[mt][2], af[mt][3], addr);
            }
            uint32_t bf[3][4];
            #pragma unroll
            for (int bp = 0; bp < 3; bp++) {
                int row = warp_n * 48 + bp * 16 + ((lane >> 4) << 3) + (lane & 7);
                int c = kk * 2 + ((lane >> 3) & 1);
                uint32_t addr = saB + (((row << 3) + (c ^ (row & 7))) << 4);
                LDSM_X4(bf[bp][0], bf[bp][1], bf[bp][2], bf[bp][3], addr);
            }
            #pragma unroll
            for (int mt = 0; mt < 2; mt++) {
                #pragma unroll
                for (int bp = 0; bp < 3; bp++) {
                    MMA_F16(acc[mt][bp * 2 + 0], af[mt], bf[bp][0], bf[bp][1]);
                    MMA_F16(acc[mt][bp * 2 + 1], af[mt], bf[bp][2], bf[bp][3]);
                }
            }
        }
        __syncthreads();
    }

    // stage C to smem
    float* Cf = (float*)smem;
    #pragma unroll
    for (int mt = 0; mt < 2; mt++) {
        #pragma unroll
        for (int j = 0; j < 6; j++) {
            int row = warp_m * 32 + mt * 16 + (lane >> 2);
            int col = warp_n * 48 + j * 8 + 2 * (lane & 3);
            Cf[col * CSTRIDE + row]           = acc[mt][j][0];
            Cf[(col + 1) * CSTRIDE + row]     = acc[mt][j][1];
            Cf[col * CSTRIDE + row + 8]       = acc[mt][j][2];
            Cf[(col + 1) * CSTRIDE + row + 8] = acc[mt][j][3];
        }
    }
    __syncthreads();

    // epilogue (plain stores)
    const int px = tid & 127;
    const int rg = tid >> 7;
    const int hw = hw0 + px;
    const size_t oimg = (size_t)bimg * RNUM;
    float ssum = 0.f;

    #pragma unroll
    for (int pass = 0; pass < 16; pass++) {
        int rloc = pass * 2 + rg;
        int r = r1 + rloc;
        if (r < RNUM) {
            float dp = Cf[rloc * CSTRIDE + px];
            float d0 = Cf[(32 + rloc) * CSTRIDE + px];
            float d1 = Cf[(64 + rloc) * CSTRIDE + px];
            float dp2 = fmaxf(2.f - 2.f * dp, 0.f);
            float d02 = fmaxf(2.f - 2.f * d0, 0.f);
            float d12 = fmaxf(2.f - 2.f * d1, 0.f);
            float dmin2 = fminf(d02, d12);
            float dpl = dp2 * rsqrtf(fmaxf(dp2, 1e-30f));
            float d0l = d02 * rsqrtf(fmaxf(d02, 1e-30f));
            float d1l = d12 * rsqrtf(fmaxf(d12, 1e-30f));
            float dminl = fminf(d0l, d1l);
            float fcn = __expf(-2.f * dmin2);
            float fpo = __expf(-2.f * dp2);
            float tt = dpl + 0.3f * (2.f - dminl);
            float fpr = __expf(-2.f * tt * tt);

            size_t base = (oimg + r) * HWSZ + hw;
            out[OFF_DIST + base]   = dpl;
            out[OFF_CLS + base]    = fpr;
            out[OFF_CLSNEG + base] = fcn;
            out[OFF_PORI + base]   = fpo;
            size_t bn = (oimg + r) * 2 * HWSZ + hw;
            out[OFF_DNEG + bn]        = d0l;
            out[OFF_DNEG + bn + HWSZ] = d1l;
            ssum += fpr;
        }
    }

    __syncthreads();
    float* sumbuf = (float*)(smem + SUMBUF_OFF);
    sumbuf[tid] = ssum;
    __syncthreads();
    if (tid < 128)
        g_part[rt][p0 + tid] = sumbuf[tid] + sumbuf[tid + 128];
}

// =====================================================================
// Kernel 4: combine partials -> 1/sum
// =====================================================================
__global__ __launch_bounds__(256) void inv_sum_kernel()
{
    int i = blockIdx.x * 256 + threadIdx.x;
    float s = 0.f;
    #pragma unroll
    for (int t = 0; t < NTILES; t++) s += g_part[t][i];
    g_sum[i] = 1.f / s;
}

// =====================================================================
// Kernel 5: cls_score *= 1/sum
// =====================================================================
__global__ __launch_bounds__(256) void scale_cls_kernel(float* __restrict__ out)
{
    int row = blockIdx.y;
    int b = row / RNUM;
    int hw = blockIdx.x * 1024 + threadIdx.x * 4;
    float4 s = *(float4*)&g_sum[b * 4096 + hw];
    float4 v = *(float4*)&out[OFF_CLS + (size_t)row * HWSZ + hw];
    v.x *= s.x; v.y *= s.y; v.z *= s.z; v.w *= s.w;
    *(float4*)&out[OFF_CLS + (size_t)row * HWSZ + hw] = v;
}

// =====================================================================
extern "C" void kernel_launch(void* const* d_in, const int* in_sizes, int n_in,
                              void* d_out, int out_size)
{
    (void)in_sizes; (void)n_in; (void)out_size;
    const float* x      = (const float*)d_in[0];
    const float* conv_w = (const float*)d_in[1];
    const float* conv_b = (const float*)d_in[2];
    const float* reps   = (const float*)d_in[3];
    const float* neg_w  = (const float*)d_in[4];
    const float* neg_b  = (const float*)d_in[5];
    float* out = (float*)d_out;

    cudaFuncSetAttribute(dml_main_kernel,
                         cudaFuncAttributeMaxDynamicSharedMemorySize, SMEM_TOT);
    cudaFuncSetAttribute(conv_mma_kernel,
                         cudaFuncAttributeMaxDynamicSharedMemorySize, CV_SMEM);

    prep_reps_kernel<<<48, 256>>>(reps, neg_w, neg_b);
    conv_mma_kernel<<<512, 512, CV_SMEM>>>(x, conv_w, conv_b);
    dml_main_kernel<<<dim3(NTILES, 512), 256, SMEM_TOT>>>(out);
    inv_sum_kernel<<<256, 256>>>();
    scale_cls_kernel<<<dim3(4, BATCH * RNUM), 256>>>(out);
}